// round 16
// baseline (speedup 1.0000x reference)
#include <cuda_runtime.h>

#define NB   16
#define HH   56
#define HW   3136
#define DIMC 256
#define NQKV 192
#define NMID 64
#define SCALE_F 0.17677669529663688f

typedef unsigned long long u64t;

// packed f32x2 helpers (SASS FFMA2 — only reachable via PTX fma.rn.f32x2)
__device__ __forceinline__ u64t pk2(float lo, float hi) {
    u64t r; asm("mov.b64 %0, {%1, %2};" : "=l"(r) : "f"(lo), "f"(hi)); return r;
}
__device__ __forceinline__ float2 upk2(u64t v) {
    float2 f; asm("mov.b64 {%0, %1}, %2;" : "=f"(f.x), "=f"(f.y) : "l"(v)); return f;
}
__device__ __forceinline__ void ffma2(u64t& d, u64t a, u64t b) {
    asm("fma.rn.f32x2 %0, %1, %2, %0;" : "+l"(d) : "l"(a), "l"(b));
}

// cp.async helpers (LDGSTS)
__device__ __forceinline__ void cp_async16(void* smem_ptr, const void* gptr) {
    unsigned sa = (unsigned)__cvta_generic_to_shared(smem_ptr);
    asm volatile("cp.async.ca.shared.global [%0], [%1], 16;" :: "r"(sa), "l"(gptr));
}
__device__ __forceinline__ void cp_commit() {
    asm volatile("cp.async.commit_group;");
}
__device__ __forceinline__ void cp_wait0() {
    asm volatile("cp.async.wait_group 0;");
}
__device__ __forceinline__ void cp_wait1() {
    asm volatile("cp.async.wait_group 1;");
}

// Scratch (static __device__ arrays — allocation-free per harness rules)
static __device__ float g_f[NB * HW * NQKV];        // [b][pixel][192] pixel-major
static __device__ float g_mid[NB * HW * NMID];      // [b][pixel][64]  pixel-major
static __device__ float g_attn[NB * 8 * 9 * HW];    // [b][h][idx][pixel] plane-major
static __device__ float g_wT[DIMC * NQKV];          // qkv_w transposed [k][n]
static __device__ float g_pT[NMID * DIMC];          // proj_w transposed [k][n]

// ---------------------------------------------------------------------------
// Kernel 0: transpose weights once (tiny)
// ---------------------------------------------------------------------------
__global__ void k_prep(const float* __restrict__ qkv_w,
                       const float* __restrict__ proj_w) {
    int stride = gridDim.x * blockDim.x;
    int i0 = blockIdx.x * blockDim.x + threadIdx.x;
    for (int i = i0; i < DIMC * NQKV; i += stride) {
        int k = i / NQKV, n = i - k * NQKV;
        g_wT[i] = qkv_w[n * DIMC + k];
    }
    for (int i = i0; i < NMID * DIMC; i += stride) {
        int k = i / DIMC, n = i - k * DIMC;
        g_pT[i] = proj_w[n * NMID + k];
    }
}

// ---------------------------------------------------------------------------
// Kernel 1: QKV GEMM v5.  C[p][n] = sum_k x[b][k][p] * qkv_w[n][k] + qkv_b[n]
// Tile: 64 pixels x 192 outputs, BK=32 (8 epochs — half the barrier bubbles).
// Dynamic smem 64 KB, cp.async double-buffered.  Same k-order as BK=16.
// ---------------------------------------------------------------------------
__global__ __launch_bounds__(256) void k_qkv(const float* __restrict__ x,
                                             const float* __restrict__ qkv_b) {
    extern __shared__ __align__(16) float dyn[];
    float* As = dyn;              // [2][32*64]  = 2 x 8 KB
    float* Bs = dyn + 4096;       // [2][32*192] = 2 x 24 KB
    const int tid = threadIdx.x;
    const int b   = blockIdx.y;
    const int p0  = blockIdx.x * 64;
    const int tn  = tid & 31;   // n lane
    const int tm  = tid >> 5;   // m group (uniform per warp)

    u64t acc[4][6];
#pragma unroll
    for (int i = 0; i < 4; i++)
#pragma unroll
        for (int j = 0; j < 6; j++) acc[i][j] = 0ull;

    const float* xb = x + (size_t)b * DIMC * HW;

    // 16B-chunk loader mapping (per 32-k stage)
    int a_kk[2], a_m4[2];
#pragma unroll
    for (int r = 0; r < 2; r++) {
        int c = tid + 256 * r;           // 0..511
        a_kk[r] = c >> 4;                // 0..31
        a_m4[r] = (c & 15) * 4;          // 0..60
    }
    int bkk[6], bc4[6];
#pragma unroll
    for (int r = 0; r < 6; r++) {
        int c = tid + 256 * r;           // 0..1535
        bkk[r] = c / 48;                 // 0..31
        bc4[r] = (c - bkk[r] * 48) * 4;  // 0..188
    }

    // prologue: stage 0 -> buffer 0
#pragma unroll
    for (int r = 0; r < 2; r++)
        cp_async16(&As[a_kk[r] * 64 + a_m4[r]],
                   xb + (size_t)a_kk[r] * HW + p0 + a_m4[r]);
#pragma unroll
    for (int r = 0; r < 6; r++)
        cp_async16(&Bs[bkk[r] * 192 + bc4[r]], g_wT + bkk[r] * NQKV + bc4[r]);
    cp_commit();

    for (int it = 0; it < 8; it++) {
        const int buf = it & 1;
        if (it + 1 < 8) {
            const int nbuf = (it + 1) & 1;
            const int kg = (it + 1) * 32;
#pragma unroll
            for (int r = 0; r < 2; r++)
                cp_async16(&As[nbuf * 2048 + a_kk[r] * 64 + a_m4[r]],
                           xb + (size_t)(kg + a_kk[r]) * HW + p0 + a_m4[r]);
#pragma unroll
            for (int r = 0; r < 6; r++)
                cp_async16(&Bs[nbuf * 6144 + bkk[r] * 192 + bc4[r]],
                           g_wT + (kg + bkk[r]) * NQKV + bc4[r]);
            cp_commit();
            cp_wait1();      // stage 'it' complete; stage it+1 in flight
        } else {
            cp_wait0();
        }
        __syncthreads();

        const float* Ab = As + buf * 2048;
        const float* Bb = Bs + buf * 6144;
#pragma unroll
        for (int kk = 0; kk < 32; kk++) {
            const u64t* Ap = (const u64t*)(Ab + kk * 64);
            const float* Bp = Bb + kk * 192;
            u64t a2[4], b2[6];
#pragma unroll
            for (int i = 0; i < 4; i++) a2[i] = Ap[8 * i + tm];   // broadcast
#pragma unroll
            for (int j = 0; j < 6; j++) {
                float bv = Bp[tn + 32 * j];                        // 128B load
                b2[j] = pk2(bv, bv);                               // splat
            }
#pragma unroll
            for (int i = 0; i < 4; i++)
#pragma unroll
                for (int j = 0; j < 6; j++) ffma2(acc[i][j], a2[i], b2[j]);
        }
        __syncthreads();   // protect buf before it gets re-filled next epoch
    }

#pragma unroll
    for (int j = 0; j < 6; j++) {
        int n = tn + 32 * j;
        float bias = qkv_b[n];
#pragma unroll
        for (int i = 0; i < 4; i++) {
            float2 v = upk2(acc[i][j]);
            size_t row = (size_t)b * HW + p0 + 16 * i + 2 * tm;
            g_f[row * NQKV + n]       = v.x + bias;
            g_f[(row + 1) * NQKV + n] = v.y + bias;
        }
    }
}

// ---------------------------------------------------------------------------
// Kernel 2a: K branch + softmax.  Channel-quad (float4 / LDS.128) version.
// ---------------------------------------------------------------------------
__global__ __launch_bounds__(224, 3) void k_attn_a(const float* __restrict__ dc_b,
                                                   const float* __restrict__ dc1_w,
                                                   const float* __restrict__ dc1_b,
                                                   const float* __restrict__ rpb) {
    __shared__ __align__(16) float4 sk4[2][6][58];   // [cq][y][x], channels 4cq..4cq+3
    __shared__ __align__(16) float4 wp4[2][81];      // [cq][idx*9+t]
    __shared__ __align__(16) float4 bias4[2][9];     // [cq][idx]
    __shared__ float srpb[9];

    const int tid  = threadIdx.x;
    const int tile = blockIdx.x;   // 0..13  (rows y0..y0+3)
    const int h    = blockIdx.y;
    const int b    = blockIdx.z;
    const int y0   = tile * 4;

    // wp4 fill: i = c*81 + idx*9 + t == dc1_w flat index
    {
        float* wp4f = (float*)wp4;
        for (int i = tid; i < 648; i += 224) {
            int c = i / 81, r = i - c * 81;
            int idx = r / 9, t = r - idx * 9;
            float v = dc1_w[i] + ((t == idx) ? 1.0f : 0.0f);
            wp4f[((c >> 2) * 81 + r) * 4 + (c & 3)] = v;
        }
        float* bias4f = (float*)bias4;
        for (int i = tid; i < 72; i += 224) {
            int c = i / 9, idx = i - c * 9;
            bias4f[((c >> 2) * 9 + idx) * 4 + (c & 3)] = dc_b[i] + dc1_b[i];
        }
        if (tid < 9) srpb[tid] = rpb[h * 9 + tid];
    }

    const float* fb = g_f + (size_t)b * HW * NQKV + h * 24;

    // halo tile (K channels): 6 rows x 58 cols, zero padded
    for (int i = tid; i < 348; i += 224) {
        int hy = i / 58, hx = i - hy * 58;
        int gy = y0 + hy - 1, gx = hx - 1;
        float4 a0, a1;
        if (gy >= 0 && gy < HH && gx >= 0 && gx < HH) {
            const float* pf = fb + (size_t)(gy * HH + gx) * NQKV;
            a0 = *(const float4*)(pf + 8);
            a1 = *(const float4*)(pf + 12);
        } else {
            a0 = a1 = make_float4(0.f, 0.f, 0.f, 0.f);
        }
        sk4[0][hy][hx] = a0;
        sk4[1][hy][hx] = a1;
    }
    __syncthreads();

    const int ty = tid / 56, tx = tid - ty * 56;
    const int p  = (y0 + ty) * HH + tx;
    const float* pf = fb + (size_t)p * NQKV;
    float4 q0 = *(const float4*)pf;
    float4 q1 = *(const float4*)(pf + 4);
    u64t q2[2][2];
    q2[0][0] = pk2(q0.x * SCALE_F, q0.y * SCALE_F);
    q2[0][1] = pk2(q0.z * SCALE_F, q0.w * SCALE_F);
    q2[1][0] = pk2(q1.x * SCALE_F, q1.y * SCALE_F);
    q2[1][1] = pk2(q1.z * SCALE_F, q1.w * SCALE_F);
    float qsum = (q0.x + q0.y + q0.z + q0.w + q1.x + q1.y + q1.z + q1.w) * SCALE_F;

    u64t logit2[9];
#pragma unroll
    for (int i = 0; i < 9; i++) logit2[i] = 0ull;

#pragma unroll
    for (int cq = 0; cq < 2; cq++) {
        ulonglong2 nb2[9];
#pragma unroll
        for (int dy = 0; dy < 3; dy++)
#pragma unroll
            for (int dx = 0; dx < 3; dx++)
                nb2[dy * 3 + dx] = *(const ulonglong2*)&sk4[cq][ty + dy][tx + dx];
        const ulonglong2* wq = (const ulonglong2*)wp4[cq];
        const ulonglong2* bq = (const ulonglong2*)bias4[cq];
        u64t qlo = q2[cq][0], qhi = q2[cq][1];
#pragma unroll
        for (int idx = 0; idx < 9; idx++) {
            ulonglong2 av = bq[idx];
#pragma unroll
            for (int t = 0; t < 9; t++) {
                ulonglong2 wv = wq[idx * 9 + t];
                ffma2(av.x, nb2[t].x, wv.x);
                ffma2(av.y, nb2[t].y, wv.y);
            }
            ffma2(logit2[idx], qlo, av.x);
            ffma2(logit2[idx], qhi, av.y);
        }
    }

    float logit[9];
#pragma unroll
    for (int idx = 0; idx < 9; idx++) {
        float2 l2 = upk2(logit2[idx]);
        logit[idx] = l2.x + l2.y + qsum * srpb[idx];
    }

    // softmax over 9 taps
    float mx = logit[0];
#pragma unroll
    for (int idx = 1; idx < 9; idx++) mx = fmaxf(mx, logit[idx]);
    float s = 0.f;
#pragma unroll
    for (int idx = 0; idx < 9; idx++) {
        logit[idx] = __expf(logit[idx] - mx);
        s += logit[idx];
    }
    float inv = 1.0f / s;

    float* pa = g_attn + (((size_t)b * 8 + h) * 9) * HW + p;
#pragma unroll
    for (int idx = 0; idx < 9; idx++)
        pa[(size_t)idx * HW] = logit[idx] * inv;     // coalesced per idx-plane
}

// ---------------------------------------------------------------------------
// Kernel 2b: V branch, channel-quad version.  attn planes -> g_mid.
// (224,4): 72-reg cap -> 4 CTAs/SM = 28 warps for latency hiding.
// ---------------------------------------------------------------------------
__global__ __launch_bounds__(224, 4) void k_attn_b(const float* __restrict__ dc_b,
                                                   const float* __restrict__ dc1_w,
                                                   const float* __restrict__ dc1_b) {
    __shared__ __align__(16) float4 sv4[2][6][58];
    __shared__ __align__(16) float4 wp4[2][81];
    __shared__ __align__(16) float4 bias4[2][9];

    const int tid  = threadIdx.x;
    const int tile = blockIdx.x;
    const int h    = blockIdx.y;
    const int b    = blockIdx.z;
    const int y0   = tile * 4;

    {
        float* wp4f = (float*)wp4;
        for (int i = tid; i < 648; i += 224) {
            int c = i / 81, r = i - c * 81;
            int idx = r / 9, t = r - idx * 9;
            float v = dc1_w[i] + ((t == idx) ? 1.0f : 0.0f);
            wp4f[((c >> 2) * 81 + r) * 4 + (c & 3)] = v;
        }
        float* bias4f = (float*)bias4;
        for (int i = tid; i < 72; i += 224) {
            int c = i / 9, idx = i - c * 9;
            bias4f[((c >> 2) * 9 + idx) * 4 + (c & 3)] = dc_b[i] + dc1_b[i];
        }
    }

    const float* fb = g_f + (size_t)b * HW * NQKV + h * 24;

    // halo tile (V channels)
    for (int i = tid; i < 348; i += 224) {
        int hy = i / 58, hx = i - hy * 58;
        int gy = y0 + hy - 1, gx = hx - 1;
        float4 c0, c1;
        if (gy >= 0 && gy < HH && gx >= 0 && gx < HH) {
            const float* pf = fb + (size_t)(gy * HH + gx) * NQKV;
            c0 = *(const float4*)(pf + 16);
            c1 = *(const float4*)(pf + 20);
        } else {
            c0 = c1 = make_float4(0.f, 0.f, 0.f, 0.f);
        }
        sv4[0][hy][hx] = c0;
        sv4[1][hy][hx] = c1;
    }
    __syncthreads();

    const int ty = tid / 56, tx = tid - ty * 56;
    const int p  = (y0 + ty) * HH + tx;

    u64t attn2[9];
    const float* pa = g_attn + (((size_t)b * 8 + h) * 9) * HW + p;
#pragma unroll
    for (int idx = 0; idx < 9; idx++) {
        float a = pa[(size_t)idx * HW];
        attn2[idx] = pk2(a, a);
    }

    float* po = g_mid + ((size_t)b * HW + p) * NMID + h * 8;

#pragma unroll
    for (int cq = 0; cq < 2; cq++) {
        ulonglong2 nb2[9];
#pragma unroll
        for (int dy = 0; dy < 3; dy++)
#pragma unroll
            for (int dx = 0; dx < 3; dx++)
                nb2[dy * 3 + dx] = *(const ulonglong2*)&sv4[cq][ty + dy][tx + dx];
        const ulonglong2* wq = (const ulonglong2*)wp4[cq];
        const ulonglong2* bq = (const ulonglong2*)bias4[cq];
        u64t olo = 0ull, ohi = 0ull;
#pragma unroll
        for (int idx = 0; idx < 9; idx++) {
            ulonglong2 av = bq[idx];
#pragma unroll
            for (int t = 0; t < 9; t++) {
                ulonglong2 wv = wq[idx * 9 + t];
                ffma2(av.x, nb2[t].x, wv.x);
                ffma2(av.y, nb2[t].y, wv.y);
            }
            ffma2(olo, attn2[idx], av.x);
            ffma2(ohi, attn2[idx], av.y);
        }
        float2 o0 = upk2(olo), o1 = upk2(ohi);
        *(float4*)(po + cq * 4) = make_float4(o0.x, o0.y, o1.x, o1.y);
    }
}

// ---------------------------------------------------------------------------
// Kernel 3: proj GEMM v4.  out[b][n][p] = sum_k mid[b][p][k]*proj_w[n][k]+pb[n]
// N-split (grid.z), tile 64 px x 128 n, BK=32 (2 epochs).  Static 48KB smem
// (A pitch 64 — A reads are broadcast, conflict-immune).  cp.async B,
// register-prefetched A.  Same k-order as BK=16.
// ---------------------------------------------------------------------------
__global__ __launch_bounds__(256) void k_proj(const float* __restrict__ proj_b,
                                              float* __restrict__ out) {
    __shared__ __align__(16) float smem_all[12288];  // 48 KB exactly
    float* As = smem_all;                    // [2][32*64]
    float* Bs = smem_all + 2 * 32 * 64;      // [2][32*128]
    const int tid = threadIdx.x;
    const int b   = blockIdx.y;
    const int p0  = blockIdx.x * 64;
    const int n0  = blockIdx.z * 128;        // n-half
    const int tn  = tid & 31;
    const int tm  = tid >> 5;

    u64t acc[4][4];
#pragma unroll
    for (int i = 0; i < 4; i++)
#pragma unroll
        for (int j = 0; j < 4; j++) acc[i][j] = 0ull;

    const float* midb = g_mid + (size_t)b * HW * NMID;

    // loader mappings
    const int a_m  = tid >> 2;           // 0..63
    const int a_kq = (tid & 3) * 8;      // 0,8,16,24
    int bkk[4], bn4[4];
#pragma unroll
    for (int r = 0; r < 4; r++) {
        int c = tid + 256 * r;           // 0..1023
        bkk[r] = c >> 5;                 // 0..31
        bn4[r] = (c & 31) * 4;           // 0..124
    }

    // prologue: A0 -> regs, B0 -> cp.async
    float4 av0 = *(const float4*)(midb + (size_t)(p0 + a_m) * NMID + a_kq);
    float4 av1 = *(const float4*)(midb + (size_t)(p0 + a_m) * NMID + a_kq + 4);
#pragma unroll
    for (int r = 0; r < 4; r++)
        cp_async16(&Bs[bkk[r] * 128 + bn4[r]], g_pT + bkk[r] * DIMC + n0 + bn4[r]);
    cp_commit();

    for (int e = 0; e < 2; e++) {
        const int buf = e;
        // commit A regs into As[buf] (transposed, pitch 64)
        {
            float* Ab = As + buf * 2048;
            Ab[(a_kq + 0) * 64 + a_m] = av0.x;
            Ab[(a_kq + 1) * 64 + a_m] = av0.y;
            Ab[(a_kq + 2) * 64 + a_m] = av0.z;
            Ab[(a_kq + 3) * 64 + a_m] = av0.w;
            Ab[(a_kq + 4) * 64 + a_m] = av1.x;
            Ab[(a_kq + 5) * 64 + a_m] = av1.y;
            Ab[(a_kq + 6) * 64 + a_m] = av1.z;
            Ab[(a_kq + 7) * 64 + a_m] = av1.w;
        }
        if (e == 0) {
#pragma unroll
            for (int r = 0; r < 4; r++)
                cp_async16(&Bs[4096 + bkk[r] * 128 + bn4[r]],
                           g_pT + (32 + bkk[r]) * DIMC + n0 + bn4[r]);
            cp_commit();
            av0 = *(const float4*)(midb + (size_t)(p0 + a_m) * NMID + 32 + a_kq);
            av1 = *(const float4*)(midb + (size_t)(p0 + a_m) * NMID + 32 + a_kq + 4);
            cp_wait1();
        } else {
            cp_wait0();
        }
        __syncthreads();

        const float* Ab = As + buf * 2048;
        const float* Bb = Bs + buf * 4096;
#pragma unroll
        for (int kk = 0; kk < 32; kk++) {
            const u64t* Ap = (const u64t*)(Ab + kk * 64);
            u64t a2[4], b2[4];
#pragma unroll
            for (int i = 0; i < 4; i++) a2[i] = Ap[8 * i + tm];
#pragma unroll
            for (int j = 0; j < 4; j++) {
                float bv = Bb[kk * 128 + tn + 32 * j];
                b2[j] = pk2(bv, bv);
            }
#pragma unroll
            for (int i = 0; i < 4; i++)
#pragma unroll
                for (int j = 0; j < 4; j++) ffma2(acc[i][j], a2[i], b2[j]);
        }
        __syncthreads();
    }

    // epilogue: 128 n-rows through padded smem (pitch 65), coalesced NCHW out
    __syncthreads();
#pragma unroll
    for (int j = 0; j < 4; j++) {
        int nl = tn + 32 * j;                 // local n 0..127
        float bias = proj_b[n0 + nl];
#pragma unroll
        for (int i = 0; i < 4; i++) {
            float2 v = upk2(acc[i][j]);
            int m = 16 * i + 2 * tm;
            smem_all[nl * 65 + m]     = v.x + bias;
            smem_all[nl * 65 + m + 1] = v.y + bias;
        }
    }
    __syncthreads();
#pragma unroll
    for (int r = 0; r < 32; r++) {
        int idx = tid + 256 * r;
        int nl = idx >> 6, m = idx & 63;
        out[((size_t)b * DIMC + n0 + nl) * HW + p0 + m] = smem_all[nl * 65 + m];
    }
}

// ---------------------------------------------------------------------------
extern "C" void kernel_launch(void* const* d_in, const int* in_sizes, int n_in,
                              void* d_out, int out_size) {
    const float* x      = (const float*)d_in[0];
    const float* qkv_w  = (const float*)d_in[1];
    const float* qkv_b  = (const float*)d_in[2];
    const float* dc_b   = (const float*)d_in[3];
    const float* dc1_w  = (const float*)d_in[4];
    const float* dc1_b  = (const float*)d_in[5];
    const float* rpb    = (const float*)d_in[6];
    const float* proj_w = (const float*)d_in[7];
    const float* proj_b = (const float*)d_in[8];
    float* out = (float*)d_out;

    // 64 KB dynamic smem opt-in for k_qkv (immediate, capture-safe, idempotent)
    cudaFuncSetAttribute(k_qkv, cudaFuncAttributeMaxDynamicSharedMemorySize, 65536);

    k_prep<<<64, 256>>>(qkv_w, proj_w);
    k_qkv<<<dim3(49, NB), 256, 65536>>>(x, qkv_b);
    k_attn_a<<<dim3(14, 8, NB), 224>>>(dc_b, dc1_w, dc1_b, rpb);
    k_attn_b<<<dim3(14, 8, NB), 224>>>(dc_b, dc1_w, dc1_b);
    k_proj<<<dim3(49, NB, 2), 256>>>(proj_b, out);
    (void)in_sizes; (void)n_in; (void)out_size;
}

// round 17
// speedup vs baseline: 1.0486x; 1.0486x over previous
#include <cuda_runtime.h>

#define NB   16
#define HH   56
#define HW   3136
#define DIMC 256
#define NQKV 192
#define NMID 64
#define SCALE_F 0.17677669529663688f

typedef unsigned long long u64t;

// packed f32x2 helpers (SASS FFMA2 — only reachable via PTX fma.rn.f32x2)
__device__ __forceinline__ u64t pk2(float lo, float hi) {
    u64t r; asm("mov.b64 %0, {%1, %2};" : "=l"(r) : "f"(lo), "f"(hi)); return r;
}
__device__ __forceinline__ float2 upk2(u64t v) {
    float2 f; asm("mov.b64 {%0, %1}, %2;" : "=f"(f.x), "=f"(f.y) : "l"(v)); return f;
}
__device__ __forceinline__ void ffma2(u64t& d, u64t a, u64t b) {
    asm("fma.rn.f32x2 %0, %1, %2, %0;" : "+l"(d) : "l"(a), "l"(b));
}

// cp.async helpers (LDGSTS)
__device__ __forceinline__ void cp_async16(void* smem_ptr, const void* gptr) {
    unsigned sa = (unsigned)__cvta_generic_to_shared(smem_ptr);
    asm volatile("cp.async.ca.shared.global [%0], [%1], 16;" :: "r"(sa), "l"(gptr));
}
__device__ __forceinline__ void cp_commit() {
    asm volatile("cp.async.commit_group;");
}
__device__ __forceinline__ void cp_wait0() {
    asm volatile("cp.async.wait_group 0;");
}
__device__ __forceinline__ void cp_wait1() {
    asm volatile("cp.async.wait_group 1;");
}

// Scratch (static __device__ arrays — allocation-free per harness rules)
static __device__ float g_f[NB * HW * NQKV];        // [b][pixel][192] pixel-major
static __device__ float g_mid[NB * HW * NMID];      // [b][pixel][64]  pixel-major
static __device__ float g_attn[NB * 8 * 9 * HW];    // [b][h][idx][pixel] plane-major
static __device__ float g_wT[DIMC * NQKV];          // qkv_w transposed [k][n]
static __device__ float g_pT[NMID * DIMC];          // proj_w transposed [k][n]

// ---------------------------------------------------------------------------
// Kernel 0: transpose weights once (tiny)
// ---------------------------------------------------------------------------
__global__ void k_prep(const float* __restrict__ qkv_w,
                       const float* __restrict__ proj_w) {
    int stride = gridDim.x * blockDim.x;
    int i0 = blockIdx.x * blockDim.x + threadIdx.x;
    for (int i = i0; i < DIMC * NQKV; i += stride) {
        int k = i / NQKV, n = i - k * NQKV;
        g_wT[i] = qkv_w[n * DIMC + k];
    }
    for (int i = i0; i < NMID * DIMC; i += stride) {
        int k = i / DIMC, n = i - k * DIMC;
        g_pT[i] = proj_w[n * NMID + k];
    }
}

// ---------------------------------------------------------------------------
// Kernel 1: QKV GEMM v4 (r15 best).  BK=16, 64px x 192n, cp.async dbl-buffer.
// ---------------------------------------------------------------------------
__global__ __launch_bounds__(256) void k_qkv(const float* __restrict__ x,
                                             const float* __restrict__ qkv_b) {
    __shared__ __align__(16) float As[2][16 * 64];    // 4 KB x2
    __shared__ __align__(16) float Bs[2][16 * 192];   // 12 KB x2
    const int tid = threadIdx.x;
    const int b   = blockIdx.y;
    const int p0  = blockIdx.x * 64;
    const int tn  = tid & 31;   // n lane
    const int tm  = tid >> 5;   // m group (uniform per warp)

    u64t acc[4][6];
#pragma unroll
    for (int i = 0; i < 4; i++)
#pragma unroll
        for (int j = 0; j < 6; j++) acc[i][j] = 0ull;

    const float* xb = x + (size_t)b * DIMC * HW;

    // 16B-chunk loader mapping
    const int a_kk  = tid >> 4;          // 0..15
    const int a_off = (tid & 15) * 4;    // 0..60
    int bkk[3], bc4[3];
#pragma unroll
    for (int r = 0; r < 3; r++) {
        int ch = tid + 256 * r;          // 0..767
        bkk[r] = ch / 48;
        bc4[r] = (ch - bkk[r] * 48) * 4;
    }

    // prologue: stage 0 -> buffer 0
    cp_async16(&As[0][a_kk * 64 + a_off], xb + (size_t)a_kk * HW + p0 + a_off);
#pragma unroll
    for (int r = 0; r < 3; r++)
        cp_async16(&Bs[0][bkk[r] * 192 + bc4[r]], g_wT + bkk[r] * NQKV + bc4[r]);
    cp_commit();

    for (int it = 0; it < 16; it++) {
        const int buf = it & 1;
        if (it + 1 < 16) {
            const int nb = (it + 1) & 1;
            const int kg = (it + 1) * 16;
            cp_async16(&As[nb][a_kk * 64 + a_off],
                       xb + (size_t)(kg + a_kk) * HW + p0 + a_off);
#pragma unroll
            for (int r = 0; r < 3; r++)
                cp_async16(&Bs[nb][bkk[r] * 192 + bc4[r]],
                           g_wT + (kg + bkk[r]) * NQKV + bc4[r]);
            cp_commit();
            cp_wait1();      // stage 'it' complete; stage it+1 in flight
        } else {
            cp_wait0();
        }
        __syncthreads();

#pragma unroll
        for (int kk = 0; kk < 16; kk++) {
            const u64t* Ap = (const u64t*)(As[buf] + kk * 64);
            const float* Bp = Bs[buf] + kk * 192;
            u64t a2[4], b2[6];
#pragma unroll
            for (int i = 0; i < 4; i++) a2[i] = Ap[8 * i + tm];   // broadcast
#pragma unroll
            for (int j = 0; j < 6; j++) {
                float bv = Bp[tn + 32 * j];                        // 128B load
                b2[j] = pk2(bv, bv);                               // splat
            }
#pragma unroll
            for (int i = 0; i < 4; i++)
#pragma unroll
                for (int j = 0; j < 6; j++) ffma2(acc[i][j], a2[i], b2[j]);
        }
        __syncthreads();   // protect buf before it gets re-filled in it+1
    }

#pragma unroll
    for (int j = 0; j < 6; j++) {
        int n = tn + 32 * j;
        float bias = qkv_b[n];
#pragma unroll
        for (int i = 0; i < 4; i++) {
            float2 v = upk2(acc[i][j]);
            size_t row = (size_t)b * HW + p0 + 16 * i + 2 * tm;
            g_f[row * NQKV + n]       = v.x + bias;
            g_f[(row + 1) * NQKV + n] = v.y + bias;
        }
    }
}

// ---------------------------------------------------------------------------
// Kernel 2a: K branch + softmax.  Channel-quad (float4 / LDS.128) version.
// ---------------------------------------------------------------------------
__global__ __launch_bounds__(224, 3) void k_attn_a(const float* __restrict__ dc_b,
                                                   const float* __restrict__ dc1_w,
                                                   const float* __restrict__ dc1_b,
                                                   const float* __restrict__ rpb) {
    __shared__ __align__(16) float4 sk4[2][6][58];   // [cq][y][x], channels 4cq..4cq+3
    __shared__ __align__(16) float4 wp4[2][81];      // [cq][idx*9+t]
    __shared__ __align__(16) float4 bias4[2][9];     // [cq][idx]
    __shared__ float srpb[9];

    const int tid  = threadIdx.x;
    const int tile = blockIdx.x;   // 0..13  (rows y0..y0+3)
    const int h    = blockIdx.y;
    const int b    = blockIdx.z;
    const int y0   = tile * 4;

    // wp4 fill: i = c*81 + idx*9 + t == dc1_w flat index
    {
        float* wp4f = (float*)wp4;
        for (int i = tid; i < 648; i += 224) {
            int c = i / 81, r = i - c * 81;
            int idx = r / 9, t = r - idx * 9;
            float v = dc1_w[i] + ((t == idx) ? 1.0f : 0.0f);
            wp4f[((c >> 2) * 81 + r) * 4 + (c & 3)] = v;
        }
        float* bias4f = (float*)bias4;
        for (int i = tid; i < 72; i += 224) {
            int c = i / 9, idx = i - c * 9;
            bias4f[((c >> 2) * 9 + idx) * 4 + (c & 3)] = dc_b[i] + dc1_b[i];
        }
        if (tid < 9) srpb[tid] = rpb[h * 9 + tid];
    }

    const float* fb = g_f + (size_t)b * HW * NQKV + h * 24;

    // halo tile (K channels): 6 rows x 58 cols, zero padded
    for (int i = tid; i < 348; i += 224) {
        int hy = i / 58, hx = i - hy * 58;
        int gy = y0 + hy - 1, gx = hx - 1;
        float4 a0, a1;
        if (gy >= 0 && gy < HH && gx >= 0 && gx < HH) {
            const float* pf = fb + (size_t)(gy * HH + gx) * NQKV;
            a0 = *(const float4*)(pf + 8);
            a1 = *(const float4*)(pf + 12);
        } else {
            a0 = a1 = make_float4(0.f, 0.f, 0.f, 0.f);
        }
        sk4[0][hy][hx] = a0;
        sk4[1][hy][hx] = a1;
    }
    __syncthreads();

    const int ty = tid / 56, tx = tid - ty * 56;
    const int p  = (y0 + ty) * HH + tx;
    const float* pf = fb + (size_t)p * NQKV;
    float4 q0 = *(const float4*)pf;
    float4 q1 = *(const float4*)(pf + 4);
    u64t q2[2][2];
    q2[0][0] = pk2(q0.x * SCALE_F, q0.y * SCALE_F);
    q2[0][1] = pk2(q0.z * SCALE_F, q0.w * SCALE_F);
    q2[1][0] = pk2(q1.x * SCALE_F, q1.y * SCALE_F);
    q2[1][1] = pk2(q1.z * SCALE_F, q1.w * SCALE_F);
    float qsum = (q0.x + q0.y + q0.z + q0.w + q1.x + q1.y + q1.z + q1.w) * SCALE_F;

    u64t logit2[9];
#pragma unroll
    for (int i = 0; i < 9; i++) logit2[i] = 0ull;

#pragma unroll
    for (int cq = 0; cq < 2; cq++) {
        ulonglong2 nb2[9];
#pragma unroll
        for (int dy = 0; dy < 3; dy++)
#pragma unroll
            for (int dx = 0; dx < 3; dx++)
                nb2[dy * 3 + dx] = *(const ulonglong2*)&sk4[cq][ty + dy][tx + dx];
        const ulonglong2* wq = (const ulonglong2*)wp4[cq];
        const ulonglong2* bq = (const ulonglong2*)bias4[cq];
        u64t qlo = q2[cq][0], qhi = q2[cq][1];
#pragma unroll
        for (int idx = 0; idx < 9; idx++) {
            ulonglong2 av = bq[idx];
#pragma unroll
            for (int t = 0; t < 9; t++) {
                ulonglong2 wv = wq[idx * 9 + t];
                ffma2(av.x, nb2[t].x, wv.x);
                ffma2(av.y, nb2[t].y, wv.y);
            }
            ffma2(logit2[idx], qlo, av.x);
            ffma2(logit2[idx], qhi, av.y);
        }
    }

    float logit[9];
#pragma unroll
    for (int idx = 0; idx < 9; idx++) {
        float2 l2 = upk2(logit2[idx]);
        logit[idx] = l2.x + l2.y + qsum * srpb[idx];
    }

    // softmax over 9 taps
    float mx = logit[0];
#pragma unroll
    for (int idx = 1; idx < 9; idx++) mx = fmaxf(mx, logit[idx]);
    float s = 0.f;
#pragma unroll
    for (int idx = 0; idx < 9; idx++) {
        logit[idx] = __expf(logit[idx] - mx);
        s += logit[idx];
    }
    float inv = 1.0f / s;

    float* pa = g_attn + (((size_t)b * 8 + h) * 9) * HW + p;
#pragma unroll
    for (int idx = 0; idx < 9; idx++)
        pa[(size_t)idx * HW] = logit[idx] * inv;     // coalesced per idx-plane
}

// ---------------------------------------------------------------------------
// Kernel 2b v2: V branch, 2 PIXELS PER THREAD (rows ty and ty+4).
// Each wp/bias LDS.128 feeds both pixels -> ~0.6x L1 wavefronts per pixel.
// Block covers 56x8 strip; grid.x = 7.  (224,2): 146-reg cap, 14 warps/SM.
// ---------------------------------------------------------------------------
__global__ __launch_bounds__(224, 2) void k_attn_b(const float* __restrict__ dc_b,
                                                   const float* __restrict__ dc1_w,
                                                   const float* __restrict__ dc1_b) {
    __shared__ __align__(16) float4 sv4[2][10][58];  // 10-row halo (8 + borders)
    __shared__ __align__(16) float4 wp4[2][81];
    __shared__ __align__(16) float4 bias4[2][9];

    const int tid  = threadIdx.x;
    const int tile = blockIdx.x;   // 0..6 (rows y0..y0+7)
    const int h    = blockIdx.y;
    const int b    = blockIdx.z;
    const int y0   = tile * 8;

    {
        float* wp4f = (float*)wp4;
        for (int i = tid; i < 648; i += 224) {
            int c = i / 81, r = i - c * 81;
            int idx = r / 9, t = r - idx * 9;
            float v = dc1_w[i] + ((t == idx) ? 1.0f : 0.0f);
            wp4f[((c >> 2) * 81 + r) * 4 + (c & 3)] = v;
        }
        float* bias4f = (float*)bias4;
        for (int i = tid; i < 72; i += 224) {
            int c = i / 9, idx = i - c * 9;
            bias4f[((c >> 2) * 9 + idx) * 4 + (c & 3)] = dc_b[i] + dc1_b[i];
        }
    }

    const float* fb = g_f + (size_t)b * HW * NQKV + h * 24;

    // halo tile (V channels): 10 rows x 58 cols, zero padded
    for (int i = tid; i < 580; i += 224) {
        int hy = i / 58, hx = i - hy * 58;
        int gy = y0 + hy - 1, gx = hx - 1;
        float4 c0, c1;
        if (gy >= 0 && gy < HH && gx >= 0 && gx < HH) {
            const float* pf = fb + (size_t)(gy * HH + gx) * NQKV;
            c0 = *(const float4*)(pf + 16);
            c1 = *(const float4*)(pf + 20);
        } else {
            c0 = c1 = make_float4(0.f, 0.f, 0.f, 0.f);
        }
        sv4[0][hy][hx] = c0;
        sv4[1][hy][hx] = c1;
    }
    __syncthreads();

    const int ty = tid / 56, tx = tid - ty * 56;   // ty 0..3
    const int pA = (y0 + ty) * HH + tx;            // pixel A: row ty
    const int pB = (y0 + ty + 4) * HH + tx;        // pixel B: row ty+4

    float attnA[9], attnB[9];
    const float* paA = g_attn + (((size_t)b * 8 + h) * 9) * HW + pA;
    const float* paB = g_attn + (((size_t)b * 8 + h) * 9) * HW + pB;
#pragma unroll
    for (int idx = 0; idx < 9; idx++) {
        attnA[idx] = paA[(size_t)idx * HW];
        attnB[idx] = paB[(size_t)idx * HW];
    }

    float* poA = g_mid + ((size_t)b * HW + pA) * NMID + h * 8;
    float* poB = g_mid + ((size_t)b * HW + pB) * NMID + h * 8;

#pragma unroll
    for (int cq = 0; cq < 2; cq++) {
        ulonglong2 nbA[9], nbB[9];
#pragma unroll
        for (int dy = 0; dy < 3; dy++)
#pragma unroll
            for (int dx = 0; dx < 3; dx++) {
                nbA[dy * 3 + dx] = *(const ulonglong2*)&sv4[cq][ty + dy][tx + dx];
                nbB[dy * 3 + dx] = *(const ulonglong2*)&sv4[cq][ty + 4 + dy][tx + dx];
            }
        const ulonglong2* wq = (const ulonglong2*)wp4[cq];
        const ulonglong2* bq = (const ulonglong2*)bias4[cq];
        u64t oAlo = 0ull, oAhi = 0ull, oBlo = 0ull, oBhi = 0ull;
#pragma unroll
        for (int idx = 0; idx < 9; idx++) {
            ulonglong2 bqv = bq[idx];
            ulonglong2 avA = bqv, avB = bqv;
#pragma unroll
            for (int t = 0; t < 9; t++) {
                ulonglong2 wv = wq[idx * 9 + t];   // loaded ONCE for both pixels
                ffma2(avA.x, nbA[t].x, wv.x);
                ffma2(avA.y, nbA[t].y, wv.y);
                ffma2(avB.x, nbB[t].x, wv.x);
                ffma2(avB.y, nbB[t].y, wv.y);
            }
            u64t atA = pk2(attnA[idx], attnA[idx]);
            u64t atB = pk2(attnB[idx], attnB[idx]);
            ffma2(oAlo, atA, avA.x);
            ffma2(oAhi, atA, avA.y);
            ffma2(oBlo, atB, avB.x);
            ffma2(oBhi, atB, avB.y);
        }
        float2 a0 = upk2(oAlo), a1 = upk2(oAhi);
        float2 b0 = upk2(oBlo), b1 = upk2(oBhi);
        *(float4*)(poA + cq * 4) = make_float4(a0.x, a0.y, a1.x, a1.y);
        *(float4*)(poB + cq * 4) = make_float4(b0.x, b0.y, b1.x, b1.y);
    }
}

// ---------------------------------------------------------------------------
// Kernel 3: proj GEMM v3 (r15 best).  N-split, 64px x 128n, BK=16.
// ---------------------------------------------------------------------------
__global__ __launch_bounds__(256) void k_proj(const float* __restrict__ proj_b,
                                              float* __restrict__ out) {
    __shared__ __align__(16) float smem_all[128 * 65];   // 33.3 KB (epilogue size)
    float* As = smem_all;                    // [2][16*66], pitch 66
    float* Bs = smem_all + 2 * 16 * 66;      // [2][16*128]
    const int tid = threadIdx.x;
    const int b   = blockIdx.y;
    const int p0  = blockIdx.x * 64;
    const int n0  = blockIdx.z * 128;        // n-half
    const int tn  = tid & 31;
    const int tm  = tid >> 5;

    u64t acc[4][4];
#pragma unroll
    for (int i = 0; i < 4; i++)
#pragma unroll
        for (int j = 0; j < 4; j++) acc[i][j] = 0ull;

    const float* midb = g_mid + (size_t)b * HW * NMID;

    // loader mappings
    const int a_m  = tid >> 2;           // 0..63
    const int a_kq = (tid & 3) * 4;      // 0,4,8,12
    int bkk[2], bn4[2];
#pragma unroll
    for (int r = 0; r < 2; r++) {
        int ch = tid + 256 * r;          // 0..511
        bkk[r] = ch >> 5;                // 0..15
        bn4[r] = (ch & 31) * 4;          // 0..124
    }

    // prologue: A0 -> regs, B0 -> cp.async
    float4 av = *(const float4*)(midb + (size_t)(p0 + a_m) * NMID + a_kq);
#pragma unroll
    for (int r = 0; r < 2; r++)
        cp_async16(&Bs[bkk[r] * 128 + bn4[r]], g_pT + bkk[r] * DIMC + n0 + bn4[r]);
    cp_commit();

    for (int e = 0; e < 4; e++) {
        const int buf = e & 1;
        // commit A regs into As[buf] (transposed)
        {
            float* Ab = As + buf * 16 * 66;
            Ab[(a_kq + 0) * 66 + a_m] = av.x;
            Ab[(a_kq + 1) * 66 + a_m] = av.y;
            Ab[(a_kq + 2) * 66 + a_m] = av.z;
            Ab[(a_kq + 3) * 66 + a_m] = av.w;
        }
        if (e + 1 < 4) {
            const int nbuf = (e + 1) & 1;
            const int kg = (e + 1) * 16;
#pragma unroll
            for (int r = 0; r < 2; r++)
                cp_async16(&Bs[nbuf * 16 * 128 + bkk[r] * 128 + bn4[r]],
                           g_pT + (kg + bkk[r]) * DIMC + n0 + bn4[r]);
            cp_commit();
            av = *(const float4*)(midb + (size_t)(p0 + a_m) * NMID + kg + a_kq);
            cp_wait1();
        } else {
            cp_wait0();
        }
        __syncthreads();

        const float* Ab = As + buf * 16 * 66;
        const float* Bb = Bs + buf * 16 * 128;
#pragma unroll
        for (int kk = 0; kk < 16; kk++) {
            const u64t* Ap = (const u64t*)(Ab + kk * 66);
            u64t a2[4], b2[4];
#pragma unroll
            for (int i = 0; i < 4; i++) a2[i] = Ap[8 * i + tm];
#pragma unroll
            for (int j = 0; j < 4; j++) {
                float bv = Bb[kk * 128 + tn + 32 * j];
                b2[j] = pk2(bv, bv);
            }
#pragma unroll
            for (int i = 0; i < 4; i++)
#pragma unroll
                for (int j = 0; j < 4; j++) ffma2(acc[i][j], a2[i], b2[j]);
        }
        __syncthreads();
    }

    // epilogue: 128 n-rows through padded smem (pitch 65), coalesced NCHW out
    __syncthreads();
#pragma unroll
    for (int j = 0; j < 4; j++) {
        int nl = tn + 32 * j;                 // local n 0..127
        float bias = proj_b[n0 + nl];
#pragma unroll
        for (int i = 0; i < 4; i++) {
            float2 v = upk2(acc[i][j]);
            int m = 16 * i + 2 * tm;
            smem_all[nl * 65 + m]     = v.x + bias;
            smem_all[nl * 65 + m + 1] = v.y + bias;
        }
    }
    __syncthreads();
#pragma unroll
    for (int r = 0; r < 32; r++) {
        int idx = tid + 256 * r;
        int nl = idx >> 6, m = idx & 63;
        out[((size_t)b * DIMC + n0 + nl) * HW + p0 + m] = smem_all[nl * 65 + m];
    }
}

// ---------------------------------------------------------------------------
extern "C" void kernel_launch(void* const* d_in, const int* in_sizes, int n_in,
                              void* d_out, int out_size) {
    const float* x      = (const float*)d_in[0];
    const float* qkv_w  = (const float*)d_in[1];
    const float* qkv_b  = (const float*)d_in[2];
    const float* dc_b   = (const float*)d_in[3];
    const float* dc1_w  = (const float*)d_in[4];
    const float* dc1_b  = (const float*)d_in[5];
    const float* rpb    = (const float*)d_in[6];
    const float* proj_w = (const float*)d_in[7];
    const float* proj_b = (const float*)d_in[8];
    float* out = (float*)d_out;

    k_prep<<<64, 256>>>(qkv_w, proj_w);
    k_qkv<<<dim3(49, NB), 256>>>(x, qkv_b);
    k_attn_a<<<dim3(14, 8, NB), 224>>>(dc_b, dc1_w, dc1_b, rpb);
    k_attn_b<<<dim3(7, 8, NB), 224>>>(dc_b, dc1_w, dc1_b);
    k_proj<<<dim3(49, NB, 2), 256>>>(proj_b, out);
    (void)in_sizes; (void)n_in; (void)out_size;
}